// round 3
// baseline (speedup 1.0000x reference)
#include <cuda_runtime.h>

#define NV 196608
#define DEG 9

// ---------------- scratch (device globals; no allocation allowed) ----------
__device__ float g_xT[(size_t)NV * 32];   // x transposed to [V, B*16]
__device__ float g_t1[(size_t)NV * 32];   // L x            [V, B*16]
__device__ float g_h1[(size_t)NV * 64];   // layer1 pre-BN  [V, B*32]
__device__ float g_t2[(size_t)NV * 64];   // L relu(bn(h1)) [V, B*32]
__device__ float g_h2[(size_t)NV * 64];   // layer2 pre-BN  [V, B*32]
__device__ float g_stats[128];            // [sum1(32), ss1(32), sum2(32), ss2(32)]
__device__ float g_sb[128];               // [scale1(32), bias1(32), scale2(32), bias2(32)]

// ---------------- K0: zero stats -------------------------------------------
__global__ void k_zero_stats() {
    if (threadIdx.x < 128) g_stats[threadIdx.x] = 0.0f;
}

// ---------------- K1: transpose x [B,V,16] -> xT [V, B*16] -----------------
__global__ void k_transpose(const float* __restrict__ x) {
    const int total = NV * 8;                     // float4 chunks
    for (int idx = blockIdx.x * blockDim.x + threadIdx.x; idx < total;
         idx += gridDim.x * blockDim.x) {
        int v = idx >> 3;
        int j = idx & 7;
        int c0 = j * 4;                           // column in [0,32)
        int b = c0 >> 4;
        int f = c0 & 15;
        float4 val = *(const float4*)(x + (size_t)b * NV * 16 + (size_t)v * 16 + f);
        *(float4*)(g_xT + (size_t)v * 32 + c0) = val;
    }
}

// ---------------- K2: t1 = L xT (width 32) ---------------------------------
__global__ void k_spmv32(const int* __restrict__ cols,
                         const float* __restrict__ vals) {
    int lane = threadIdx.x & 31;
    int gw = (blockIdx.x * blockDim.x + threadIdx.x) >> 5;
    int nw = (gridDim.x * blockDim.x) >> 5;
    for (int v = gw; v < NV; v += nw) {
        size_t eb = (size_t)v * DEG;
        int cj = 0; float aj = 0.0f;
        if (lane < DEG) { cj = cols[eb + lane]; aj = vals[eb + lane]; }
        int   c9[DEG]; float a9[DEG], g9[DEG];
        #pragma unroll
        for (int j = 0; j < DEG; j++) {
            c9[j] = __shfl_sync(0xffffffffu, cj, j);
            a9[j] = __shfl_sync(0xffffffffu, aj, j);
        }
        #pragma unroll
        for (int j = 0; j < DEG; j++)
            g9[j] = g_xT[(size_t)c9[j] * 32 + lane];
        float s = 0.0f;
        #pragma unroll
        for (int j = 0; j < DEG; j++) s = fmaf(a9[j], g9[j], s);
        g_t1[(size_t)v * 32 + lane] = s;
    }
}

// ---------------- K3: fused layer1: s = L t1; h1 = xT*(W0-W2)+t1*W1+s*2W2 --
__global__ void k_fused1(const int* __restrict__ cols,
                         const float* __restrict__ vals,
                         const float* __restrict__ W1) {
    __shared__ float sW[3][16 * 32];
    __shared__ float sIn[8][3][32];
    __shared__ float bsum[32], bss[32];
    int tid = threadIdx.x;
    for (int i = tid; i < 512; i += blockDim.x) {
        float w0 = W1[i], w1 = W1[512 + i], w2 = W1[1024 + i];
        sW[0][i] = w0 - w2; sW[1][i] = w1; sW[2][i] = 2.0f * w2;
    }
    if (tid < 32) { bsum[tid] = 0.0f; bss[tid] = 0.0f; }
    __syncthreads();

    int lane = tid & 31, w = tid >> 5;
    int gw = blockIdx.x * 8 + w, nw = gridDim.x * 8;
    float ls = 0.0f, lss = 0.0f;
    for (int v = gw; v < NV; v += nw) {
        size_t eb = (size_t)v * DEG;
        int cj = 0; float aj = 0.0f;
        if (lane < DEG) { cj = cols[eb + lane]; aj = vals[eb + lane]; }
        int c9[DEG]; float a9[DEG], g9[DEG];
        #pragma unroll
        for (int j = 0; j < DEG; j++) {
            c9[j] = __shfl_sync(0xffffffffu, cj, j);
            a9[j] = __shfl_sync(0xffffffffu, aj, j);
        }
        #pragma unroll
        for (int j = 0; j < DEG; j++)
            g9[j] = g_t1[(size_t)c9[j] * 32 + lane];
        float s = 0.0f;
        #pragma unroll
        for (int j = 0; j < DEG; j++) s = fmaf(a9[j], g9[j], s);

        float xv = g_xT[(size_t)v * 32 + lane];
        float tv = g_t1[(size_t)v * 32 + lane];
        sIn[w][0][lane] = xv; sIn[w][1][lane] = tv; sIn[w][2][lane] = s;
        __syncwarp();
        float acc0 = 0.0f, acc1 = 0.0f;
        #pragma unroll
        for (int f = 0; f < 16; f++) {
            float wa = sW[0][f * 32 + lane];
            float wb = sW[1][f * 32 + lane];
            float wc = sW[2][f * 32 + lane];
            acc0 = fmaf(sIn[w][0][f], wa, acc0);
            acc0 = fmaf(sIn[w][1][f], wb, acc0);
            acc0 = fmaf(sIn[w][2][f], wc, acc0);
            acc1 = fmaf(sIn[w][0][16 + f], wa, acc1);
            acc1 = fmaf(sIn[w][1][16 + f], wb, acc1);
            acc1 = fmaf(sIn[w][2][16 + f], wc, acc1);
        }
        __syncwarp();
        g_h1[(size_t)v * 64 + lane] = acc0;
        g_h1[(size_t)v * 64 + 32 + lane] = acc1;
        ls += acc0 + acc1;
        lss = fmaf(acc0, acc0, lss);
        lss = fmaf(acc1, acc1, lss);
    }
    atomicAdd(&bsum[lane], ls);
    atomicAdd(&bss[lane], lss);
    __syncthreads();
    if (tid < 32) {
        atomicAdd(&g_stats[tid], bsum[tid]);
        atomicAdd(&g_stats[32 + tid], bss[tid]);
    }
}

// ---------------- K4: finalize BN stats -> scale/bias ----------------------
__global__ void k_finalize(const float* __restrict__ gamma,
                           const float* __restrict__ beta, int which) {
    int c = threadIdx.x;
    if (c >= 32) return;
    float n = (float)(2 * NV);
    float sum = g_stats[which * 64 + c];
    float ss = g_stats[which * 64 + 32 + c];
    float mean = sum / n;
    float var = ss / n - mean * mean;
    float rstd = rsqrtf(var + 1e-5f);
    float sc = gamma[c] * rstd;
    g_sb[which * 64 + c] = sc;
    g_sb[which * 64 + 32 + c] = beta[c] - mean * sc;
}

// ---------------- K5: t2 = L relu(bn(h1)) (width 64, bn fused on gather) ---
__global__ void k_spmv64_bn(const int* __restrict__ cols,
                            const float* __restrict__ vals) {
    int lane = threadIdx.x & 31;
    int gw = (blockIdx.x * blockDim.x + threadIdx.x) >> 5;
    int nw = (gridDim.x * blockDim.x) >> 5;
    int c0 = (2 * lane) & 31;
    float sc0 = g_sb[c0],     bi0 = g_sb[32 + c0];
    float sc1 = g_sb[c0 + 1], bi1 = g_sb[32 + c0 + 1];
    for (int v = gw; v < NV; v += nw) {
        size_t eb = (size_t)v * DEG;
        int cj = 0; float aj = 0.0f;
        if (lane < DEG) { cj = cols[eb + lane]; aj = vals[eb + lane]; }
        int c9[DEG]; float a9[DEG]; float2 g9[DEG];
        #pragma unroll
        for (int j = 0; j < DEG; j++) {
            c9[j] = __shfl_sync(0xffffffffu, cj, j);
            a9[j] = __shfl_sync(0xffffffffu, aj, j);
        }
        #pragma unroll
        for (int j = 0; j < DEG; j++)
            g9[j] = *(const float2*)(g_h1 + (size_t)c9[j] * 64 + 2 * lane);
        float sx = 0.0f, sy = 0.0f;
        #pragma unroll
        for (int j = 0; j < DEG; j++) {
            float r0 = fmaxf(fmaf(g9[j].x, sc0, bi0), 0.0f);
            float r1 = fmaxf(fmaf(g9[j].y, sc1, bi1), 0.0f);
            sx = fmaf(a9[j], r0, sx);
            sy = fmaf(a9[j], r1, sy);
        }
        float2 out; out.x = sx; out.y = sy;
        *(float2*)(g_t2 + (size_t)v * 64 + 2 * lane) = out;
    }
}

// ---------------- K6: fused layer2 ----------------------------------------
__global__ void k_fused2(const int* __restrict__ cols,
                         const float* __restrict__ vals,
                         const float* __restrict__ W2) {
    __shared__ float sW[3][32 * 32];
    __shared__ float sIn[8][3][64];
    __shared__ float bsum[32], bss[32];
    int tid = threadIdx.x;
    for (int i = tid; i < 1024; i += blockDim.x) {
        float w0 = W2[i], w1 = W2[1024 + i], w2 = W2[2048 + i];
        sW[0][i] = w0 - w2; sW[1][i] = w1; sW[2][i] = 2.0f * w2;
    }
    if (tid < 32) { bsum[tid] = 0.0f; bss[tid] = 0.0f; }
    __syncthreads();

    int lane = tid & 31, w = tid >> 5;
    int gw = blockIdx.x * 8 + w, nw = gridDim.x * 8;
    int c0 = (2 * lane) & 31;
    float sc0 = g_sb[c0],     bi0 = g_sb[32 + c0];
    float sc1 = g_sb[c0 + 1], bi1 = g_sb[32 + c0 + 1];
    float ls = 0.0f, lss = 0.0f;
    for (int v = gw; v < NV; v += nw) {
        size_t eb = (size_t)v * DEG;
        int cj = 0; float aj = 0.0f;
        if (lane < DEG) { cj = cols[eb + lane]; aj = vals[eb + lane]; }
        int c9[DEG]; float a9[DEG]; float2 g9[DEG];
        #pragma unroll
        for (int j = 0; j < DEG; j++) {
            c9[j] = __shfl_sync(0xffffffffu, cj, j);
            a9[j] = __shfl_sync(0xffffffffu, aj, j);
        }
        #pragma unroll
        for (int j = 0; j < DEG; j++)
            g9[j] = *(const float2*)(g_t2 + (size_t)c9[j] * 64 + 2 * lane);
        float sx = 0.0f, sy = 0.0f;
        #pragma unroll
        for (int j = 0; j < DEG; j++) {
            sx = fmaf(a9[j], g9[j].x, sx);
            sy = fmaf(a9[j], g9[j].y, sy);
        }
        // streamed inputs: a1 = relu(bn(h1[v])), t2v = t2[v]
        float2 hv = *(const float2*)(g_h1 + (size_t)v * 64 + 2 * lane);
        float a1x = fmaxf(fmaf(hv.x, sc0, bi0), 0.0f);
        float a1y = fmaxf(fmaf(hv.y, sc1, bi1), 0.0f);
        float2 tv = *(const float2*)(g_t2 + (size_t)v * 64 + 2 * lane);

        sIn[w][0][2 * lane] = a1x;  sIn[w][0][2 * lane + 1] = a1y;
        sIn[w][1][2 * lane] = tv.x; sIn[w][1][2 * lane + 1] = tv.y;
        sIn[w][2][2 * lane] = sx;   sIn[w][2][2 * lane + 1] = sy;
        __syncwarp();
        float acc0 = 0.0f, acc1 = 0.0f;
        #pragma unroll
        for (int f = 0; f < 32; f++) {
            float wa = sW[0][f * 32 + lane];
            float wb = sW[1][f * 32 + lane];
            float wc = sW[2][f * 32 + lane];
            acc0 = fmaf(sIn[w][0][f], wa, acc0);
            acc0 = fmaf(sIn[w][1][f], wb, acc0);
            acc0 = fmaf(sIn[w][2][f], wc, acc0);
            acc1 = fmaf(sIn[w][0][32 + f], wa, acc1);
            acc1 = fmaf(sIn[w][1][32 + f], wb, acc1);
            acc1 = fmaf(sIn[w][2][32 + f], wc, acc1);
        }
        __syncwarp();
        g_h2[(size_t)v * 64 + lane] = acc0;
        g_h2[(size_t)v * 64 + 32 + lane] = acc1;
        ls += acc0 + acc1;
        lss = fmaf(acc0, acc0, lss);
        lss = fmaf(acc1, acc1, lss);
    }
    atomicAdd(&bsum[lane], ls);
    atomicAdd(&bss[lane], lss);
    __syncthreads();
    if (tid < 32) {
        atomicAdd(&g_stats[64 + tid], bsum[tid]);
        atomicAdd(&g_stats[96 + tid], bss[tid]);
    }
}

// ---------------- K8: out[b,v,c] = relu(bn2(h2)) ---------------------------
__global__ void k_output(float* __restrict__ out) {
    const int total = NV * 16;                    // float4 chunks of h2 rows
    for (int idx = blockIdx.x * blockDim.x + threadIdx.x; idx < total;
         idx += gridDim.x * blockDim.x) {
        int v = idx >> 4;
        int j = idx & 15;
        int col = j * 4;                          // 0..63
        int ch = col & 31;
        int b = col >> 5;
        float4 hv = *(const float4*)(g_h2 + (size_t)v * 64 + col);
        float4 r;
        r.x = fmaxf(fmaf(hv.x, g_sb[64 + ch],     g_sb[96 + ch]),     0.0f);
        r.y = fmaxf(fmaf(hv.y, g_sb[64 + ch + 1], g_sb[96 + ch + 1]), 0.0f);
        r.z = fmaxf(fmaf(hv.z, g_sb[64 + ch + 2], g_sb[96 + ch + 2]), 0.0f);
        r.w = fmaxf(fmaf(hv.w, g_sb[64 + ch + 3], g_sb[96 + ch + 3]), 0.0f);
        *(float4*)(out + (size_t)b * NV * 32 + (size_t)v * 32 + ch) = r;
    }
}

// ---------------- launch ----------------------------------------------------
extern "C" void kernel_launch(void* const* d_in, const int* in_sizes, int n_in,
                              void* d_out, int out_size) {
    const float* x    = (const float*)d_in[0];
    const int*   cols = (const int*)d_in[2];
    const float* vals = (const float*)d_in[3];
    const float* W1   = (const float*)d_in[4];
    const float* g1   = (const float*)d_in[5];
    const float* b1   = (const float*)d_in[6];
    const float* W2   = (const float*)d_in[7];
    const float* g2   = (const float*)d_in[8];
    const float* b2   = (const float*)d_in[9];
    float*       out  = (float*)d_out;

    const int BLK = 256;
    const int GRID_SPMV = 1184;    // 148 SMs * 8 blocks

    k_zero_stats<<<1, 128>>>();
    k_transpose<<<2048, BLK>>>(x);
    k_spmv32<<<GRID_SPMV, BLK>>>(cols, vals);
    k_fused1<<<GRID_SPMV, BLK>>>(cols, vals, W1);
    k_finalize<<<1, 32>>>(g1, b1, 0);
    k_spmv64_bn<<<GRID_SPMV, BLK>>>(cols, vals);
    k_fused2<<<GRID_SPMV, BLK>>>(cols, vals, W2);
    k_finalize<<<1, 32>>>(g2, b2, 1);
    k_output<<<2048, BLK>>>(out);
}